// round 4
// baseline (speedup 1.0000x reference)
#include <cuda_runtime.h>
#include <cuda_fp16.h>
#include <cstdint>

#define C_   8
#define N_   1024
#define T_   3
#define INF_ 64
#define H_   4
#define F_   64
#define K_   256      // H*F
#define S_   192      // T*F
#define E_   65536
#define CN_  8192

// ---------------- scratch (device globals; no runtime allocs) ----------------
__device__ __align__(16) float  g_P[C_*T_*N_*K_];          // [c][t][n][k]  25.2MB
__device__ __align__(16) float  g_msrc[CN_];
__device__ __align__(16) float  g_mdst[CN_];
__device__ __align__(16) float  g_asrc[C_*N_*H_];          // [c][v][h]
__device__ __align__(16) float  g_adst[C_*N_*H_];          // [c][u][h]
__device__ __align__(16) __half g_Fd[(size_t)C_*H_*N_*S_]; // [c*4+h][u][s]  12.6MB
__device__ __align__(16) __half g_At[(size_t)C_*H_*N_*N_]; // [c*4+h][v][u]  67MB

// ---------------- helpers ----------------
__device__ __forceinline__ float clipf(float x) {
    return fminf(fmaxf(x, -1e9f), 1e9f);
}

// fast exp via 2^(x*log2e), degree-6 poly (rel err ~1e-7), FMA-pipe only
__device__ __forceinline__ float fexp(float x) {
    float y  = x * 1.4426950408889634f;
    int   ni = __float2int_rn(y);
    float f  = y - (float)ni;
    float p  = 1.5403530393381608e-4f;
    p = fmaf(p, f, 1.3333558146428443e-3f);
    p = fmaf(p, f, 9.6181291076284770e-3f);
    p = fmaf(p, f, 5.5504108664821580e-2f);
    p = fmaf(p, f, 2.4022650695910071e-1f);
    p = fmaf(p, f, 6.9314718055994531e-1f);
    p = fmaf(p, f, 1.0f);
    return __int_as_float((ni + 127) << 23) * p;
}

// ---------------- K0a: zero masks ----------------
__global__ __launch_bounds__(256) void k_zero_masks() {
    int i = blockIdx.x * 256 + threadIdx.x;
    if (i < CN_) { g_msrc[i] = 0.f; g_mdst[i] = 0.f; }
}

// ---------------- K0b: zero outs ----------------
__global__ __launch_bounds__(256) void k_zero_outs(float* __restrict__ outs) {
    int i = blockIdx.x * 256 + threadIdx.x;   // float4 index
    reinterpret_cast<float4*>(outs)[i] = make_float4(0.f, 0.f, 0.f, 0.f);
}

// ---------------- K1: scatter edge masks (edge_idx is int32 — JAX x64 disabled) ----------------
__global__ __launch_bounds__(256) void k_scatter(const int* __restrict__ edge) {
    int i = blockIdx.x * 256 + threadIdx.x;
    if (i < E_) {
        g_msrc[edge[i]      & (CN_ - 1)] = 1.f;
        g_mdst[edge[E_ + i] & (CN_ - 1)] = 1.f;
    }
}

// ---------------- K2: feat GEMM -> P[c][t][n][k] ----------------
__global__ __launch_bounds__(256) void k_feat(const float* __restrict__ nf,
                                              const float* __restrict__ fc) {
    int n0 = blockIdx.x * 32;
    int t  = blockIdx.y;
    int c  = blockIdx.z;
    __shared__ __align__(16) float As[32 * 64];

    #pragma unroll
    for (int l = 0; l < 2; ++l) {
        int idx4 = threadIdx.x + l * 256;
        int r = idx4 >> 4, i4 = idx4 & 15;
        const float4 v = *reinterpret_cast<const float4*>(
            nf + (size_t)((c * N_ + n0 + r) * T_ + t) * INF_ + i4 * 4);
        reinterpret_cast<float4*>(As)[idx4] = v;
    }
    __syncthreads();

    int k = threadIdx.x;
    const float* fcp = fc + (size_t)t * INF_ * K_ + k;
    float acc[32];
    #pragma unroll
    for (int r = 0; r < 32; ++r) acc[r] = 0.f;

    for (int i4 = 0; i4 < 16; ++i4) {
        float b0 = fcp[(i4 * 4 + 0) * K_];
        float b1 = fcp[(i4 * 4 + 1) * K_];
        float b2 = fcp[(i4 * 4 + 2) * K_];
        float b3 = fcp[(i4 * 4 + 3) * K_];
        #pragma unroll
        for (int r = 0; r < 32; ++r) {
            float4 a = reinterpret_cast<const float4*>(As)[r * 16 + i4];
            acc[r] = fmaf(a.x, b0, acc[r]);
            acc[r] = fmaf(a.y, b1, acc[r]);
            acc[r] = fmaf(a.z, b2, acc[r]);
            acc[r] = fmaf(a.w, b3, acc[r]);
        }
    }
    float* dst = g_P + (size_t)((c * T_ + t) * N_ + n0) * K_ + k;
    #pragma unroll
    for (int r = 0; r < 32; ++r) dst[r * K_] = acc[r];
}

// ---------------- K3: a_src/a_dst reductions + Fd (fp16) ----------------
// feat_flat[(c,u),h,s] = P_flat[c*786432 + u*768 + (s/64)*256 + h*64 + (s%64)]
__global__ __launch_bounds__(256) void k_reduce(const float* __restrict__ attn_src,
                                                const float* __restrict__ attn_dst) {
    int W    = blockIdx.x * 8 + (threadIdx.x >> 5);
    int lane = threadIdx.x & 31;
    int c = W >> 12;
    int u = (W >> 2) & 1023;
    int h = W & 3;

    float ms = g_msrc[c * N_ + u];
    float md = g_mdst[c * N_ + u];
    int pbase = c * 786432 + u * 768 + h * 64;

    float sa = 0.f, sd = 0.f;
    #pragma unroll
    for (int j = 0; j < 6; ++j) {
        int s = lane + 32 * j;
        int b = s >> 6, f = s & 63;
        float val = g_P[pbase + b * 256 + f];
        sa += clipf(val * attn_src[h * S_ + s]);
        sd += clipf(val * attn_dst[h * S_ + s]);
        g_Fd[((size_t)(c * 4 + h) * N_ + u) * S_ + s] = __float2half(val * md);
    }
    #pragma unroll
    for (int o = 16; o; o >>= 1) {
        sa += __shfl_down_sync(0xffffffffu, sa, o);
        sd += __shfl_down_sync(0xffffffffu, sd, o);
    }
    if (lane == 0) {
        g_asrc[(c * N_ + u) * H_ + h] = ms * sa;
        g_adst[(c * N_ + u) * H_ + h] = md * sd;
    }
}

// ---------------- K4: softmax over c -> a (fp32 out) + At (fp16 transposed) ----------------
__global__ __launch_bounds__(256) void k_attn_a(float* __restrict__ a_out) {
    int v = blockIdx.y;
    int u = blockIdx.x * 256 + threadIdx.x;
    __shared__ float s_asrc[32];
    if (threadIdx.x < 32) {
        int c = threadIdx.x >> 2, h = threadIdx.x & 3;
        s_asrc[threadIdx.x] = g_asrc[(c * N_ + v) * H_ + h];
    }
    __syncthreads();

    float e[8][4];
    float den[4] = {0.f, 0.f, 0.f, 0.f};
    #pragma unroll
    for (int c = 0; c < 8; ++c) {
        float4 d = *reinterpret_cast<const float4*>(&g_adst[(c * N_ + u) * H_]);
        float zd[4] = {d.x, d.y, d.z, d.w};
        #pragma unroll
        for (int h = 0; h < 4; ++h) {
            float z = s_asrc[c * 4 + h] + zd[h];
            z = (z >= 0.f) ? z : 0.2f * z;     // leaky relu
            z = clipf(z);
            float ee = fexp(z);
            e[c][h] = ee;
            den[h] += ee;
        }
    }
    float inv[4];
    #pragma unroll
    for (int h = 0; h < 4; ++h) inv[h] = 1.0f / den[h];

    #pragma unroll
    for (int c = 0; c < 8; ++c) {
        float a0 = e[c][0] * inv[0];
        float a1 = e[c][1] * inv[1];
        float a2 = e[c][2] * inv[2];
        float a3 = e[c][3] * inv[3];
        reinterpret_cast<float4*>(a_out)[(size_t)(c * N_ + v) * N_ + u] =
            make_float4(a0, a1, a2, a3);
        g_At[((size_t)(c * 4 + 0) * N_ + v) * N_ + u] = __float2half(a0);
        g_At[((size_t)(c * 4 + 1) * N_ + v) * N_ + u] = __float2half(a1);
        g_At[((size_t)(c * 4 + 2) * N_ + v) * N_ + u] = __float2half(a2);
        g_At[((size_t)(c * 4 + 3) * N_ + v) * N_ + u] = __float2half(a3);
    }
}

// ---------------- K5: m = A @ Fd per (c,h); mma.sync, manual fragment loads ----------------
// grid (16 v-tiles, 32 ch), block 256 = 8 warps (2 x 4 over 64v x 192f)
#define LDA 72
#define LDB 200
__global__ __launch_bounds__(256) void k_m(float* __restrict__ outs) {
    __shared__ __align__(16) __half a_s[64 * LDA];
    __shared__ __align__(16) __half b_s[64 * LDB];

    int ch = blockIdx.y;
    int c  = ch >> 2;
    int v0 = blockIdx.x * 64;
    int tid = threadIdx.x;
    int lane = tid & 31, wid = tid >> 5;
    int wv = wid >> 2, wf = wid & 3;
    int g  = lane >> 2;            // groupID 0..7
    int t2 = (lane & 3) * 2;       // 0,2,4,6

    const __half* Ag = g_At + (size_t)ch * N_ * N_ + (size_t)v0 * N_;
    const __half* Bg = g_Fd + (size_t)ch * N_ * S_;

    float acc[2][6][4];
    #pragma unroll
    for (int mi = 0; mi < 2; ++mi)
        #pragma unroll
        for (int ni = 0; ni < 6; ++ni)
            #pragma unroll
            for (int q = 0; q < 4; ++q) acc[mi][ni][q] = 0.f;

    int r = tid >> 2, seg = tid & 3;

    for (int u0 = 0; u0 < N_; u0 += 64) {
        const int4* ap = reinterpret_cast<const int4*>(Ag + (size_t)r * N_ + u0 + seg * 16);
        int4 av0 = ap[0], av1 = ap[1];
        const int4* bp = reinterpret_cast<const int4*>(Bg + (size_t)(u0 + r) * S_ + seg * 48);
        int4 bv[6];
        #pragma unroll
        for (int j = 0; j < 6; ++j) bv[j] = bp[j];

        int4* ad = reinterpret_cast<int4*>(a_s + r * LDA + seg * 16);
        ad[0] = av0; ad[1] = av1;
        int4* bd = reinterpret_cast<int4*>(b_s + r * LDB + seg * 48);
        #pragma unroll
        for (int j = 0; j < 6; ++j) bd[j] = bv[j];
        __syncthreads();

        #pragma unroll
        for (int ki = 0; ki < 4; ++ki) {
            int k0 = ki * 16;
            uint32_t af[2][4];
            #pragma unroll
            for (int mi = 0; mi < 2; ++mi) {
                int row0 = wv * 32 + mi * 16 + g;
                const __half* A0 = a_s + row0 * LDA + k0;
                af[mi][0] = *reinterpret_cast<const uint32_t*>(A0 + t2);
                af[mi][1] = *reinterpret_cast<const uint32_t*>(A0 + 8 * LDA + t2);
                af[mi][2] = *reinterpret_cast<const uint32_t*>(A0 + t2 + 8);
                af[mi][3] = *reinterpret_cast<const uint32_t*>(A0 + 8 * LDA + t2 + 8);
            }
            #pragma unroll
            for (int ni = 0; ni < 6; ++ni) {
                int n = wf * 48 + ni * 8 + g;
                const __half* B0 = b_s + (k0 + t2) * LDB + n;
                uint32_t lo0 = *reinterpret_cast<const unsigned short*>(B0);
                uint32_t hi0 = *reinterpret_cast<const unsigned short*>(B0 + LDB);
                uint32_t lo1 = *reinterpret_cast<const unsigned short*>(B0 + 8 * LDB);
                uint32_t hi1 = *reinterpret_cast<const unsigned short*>(B0 + 9 * LDB);
                uint32_t b0 = lo0 | (hi0 << 16);
                uint32_t b1 = lo1 | (hi1 << 16);
                #pragma unroll
                for (int mi = 0; mi < 2; ++mi) {
                    asm volatile(
                        "mma.sync.aligned.m16n8k16.row.col.f32.f16.f16.f32 "
                        "{%0,%1,%2,%3},{%4,%5,%6,%7},{%8,%9},{%0,%1,%2,%3};"
                        : "+f"(acc[mi][ni][0]), "+f"(acc[mi][ni][1]),
                          "+f"(acc[mi][ni][2]), "+f"(acc[mi][ni][3])
                        : "r"(af[mi][0]), "r"(af[mi][1]), "r"(af[mi][2]), "r"(af[mi][3]),
                          "r"(b0), "r"(b1));
                }
            }
        }
        __syncthreads();
    }

    // epilogue: relu then atomic-add across h into outs[(c*N+v)*192 + s]
    #pragma unroll
    for (int mi = 0; mi < 2; ++mi) {
        #pragma unroll
        for (int ni = 0; ni < 6; ++ni) {
            int v = v0 + wv * 32 + mi * 16 + g;
            int f = wf * 48 + ni * 8 + t2;
            float* o0 = outs + (size_t)(c * N_ + v) * S_ + f;
            atomicAdd(o0,     fmaxf(acc[mi][ni][0], 0.f));
            atomicAdd(o0 + 1, fmaxf(acc[mi][ni][1], 0.f));
            float* o1 = outs + (size_t)(c * N_ + v + 8) * S_ + f;
            atomicAdd(o1,     fmaxf(acc[mi][ni][2], 0.f));
            atomicAdd(o1 + 1, fmaxf(acc[mi][ni][3], 0.f));
        }
    }
}

// ---------------- launch ----------------
extern "C" void kernel_launch(void* const* d_in, const int* in_sizes, int n_in,
                              void* d_out, int out_size) {
    const int*   edge = (const int*)d_in[0];
    const float* nf   = (const float*)d_in[1];
    const float* fc   = (const float*)d_in[2];
    const float* asv  = (const float*)d_in[3];
    const float* adv  = (const float*)d_in[4];

    float* outs  = (float*)d_out;                          // (8,1024,3,64)
    float* a_out = outs + (size_t)C_ * N_ * T_ * F_;       // (8,1024,1024,4)

    k_zero_outs<<<(C_ * N_ * T_ * F_ / 4) / 256, 256>>>(outs);
    k_zero_masks<<<32, 256>>>();
    k_scatter<<<E_ / 256, 256>>>(edge);
    k_feat<<<dim3(32, 3, 8), 256>>>(nf, fc);
    k_reduce<<<4096, 256>>>(asv, adv);
    k_attn_a<<<dim3(4, N_), 256>>>(a_out);
    k_m<<<dim3(16, 32), 256>>>(outs);
}

// round 6
// speedup vs baseline: 1.1653x; 1.1653x over previous
#include <cuda_runtime.h>
#include <cuda_fp16.h>
#include <cstdint>

#define C_   8
#define N_   1024
#define T_   3
#define INF_ 64
#define H_   4
#define F_   64
#define K_   256      // H*F
#define S_   192      // T*F
#define E_   65536
#define CN_  8192

typedef unsigned long long ull;

// ---------------- scratch ----------------
__device__ __align__(16) float  g_msrc[CN_];
__device__ __align__(16) float  g_mdst[CN_];
__device__ __align__(16) float  g_asrc[C_*N_*H_];          // RAW (pre-msrc) accumulators
__device__ __align__(16) float  g_adst[C_*N_*H_];          // RAW (mdst already folded via Fd path weights? no: raw*mdst at read)
__device__ __align__(16) __half g_Fd[(size_t)C_*H_*N_*S_]; // [c*4+h][u][s]  12.6MB
__device__ __align__(16) __half g_At[(size_t)C_*H_*N_*N_]; // [c*4+h][v][u]  67MB

// ---------------- helpers ----------------
__device__ __forceinline__ float clipf(float x) {
    return fminf(fmaxf(x, -1e9f), 1e9f);
}
__device__ __forceinline__ float fexp(float x) {
    float y  = x * 1.4426950408889634f;
    int   ni = __float2int_rn(y);
    float f  = y - (float)ni;
    float p  = 1.5403530393381608e-4f;
    p = fmaf(p, f, 1.3333558146428443e-3f);
    p = fmaf(p, f, 9.6181291076284770e-3f);
    p = fmaf(p, f, 5.5504108664821580e-2f);
    p = fmaf(p, f, 2.4022650695910071e-1f);
    p = fmaf(p, f, 6.9314718055994531e-1f);
    p = fmaf(p, f, 1.0f);
    return __int_as_float((ni + 127) << 23) * p;
}
__device__ __forceinline__ uint32_t smem_u32(const void* p) {
    return (uint32_t)__cvta_generic_to_shared(p);
}
__device__ __forceinline__ ull fma2(ull a, ull b, ull c) {
    ull d; asm("fma.rn.f32x2 %0, %1, %2, %3;" : "=l"(d) : "l"(a), "l"(b), "l"(c));
    return d;
}
__device__ __forceinline__ ull dup2(float x) {
    ull d; asm("mov.b64 %0, {%1,%1};" : "=l"(d) : "f"(x)); return d;
}
__device__ __forceinline__ void unpack2(ull v, float& lo, float& hi) {
    asm("mov.b64 {%0,%1}, %2;" : "=f"(lo), "=f"(hi) : "l"(v));
}
__device__ __forceinline__ float sel3(float a0, float a1, float a2, int b) {
    return (b == 0) ? a0 : ((b == 1) ? a1 : a2);
}

// ---------------- K0a: zero scratch ----------------
__global__ __launch_bounds__(256) void k_zero_scratch() {
    int i = blockIdx.x * 256 + threadIdx.x;
    if (i < CN_) { g_msrc[i] = 0.f; g_mdst[i] = 0.f; }
    if (i < C_*N_*H_) { g_asrc[i] = 0.f; g_adst[i] = 0.f; }
}
// ---------------- K0b: zero outs ----------------
__global__ __launch_bounds__(256) void k_zero_outs(float* __restrict__ outs) {
    int i = blockIdx.x * 256 + threadIdx.x;
    reinterpret_cast<float4*>(outs)[i] = make_float4(0.f, 0.f, 0.f, 0.f);
}
// ---------------- K1: scatter edge masks (int32) ----------------
__global__ __launch_bounds__(256) void k_scatter(const int* __restrict__ edge) {
    int i = blockIdx.x * 256 + threadIdx.x;
    if (i < E_) {
        g_msrc[edge[i]      & (CN_ - 1)] = 1.f;
        g_mdst[edge[E_ + i] & (CN_ - 1)] = 1.f;
    }
}

// ---------------- K2: fused feat GEMM (f32x2) + scrambled Fd write + asrc/adst partials ----------------
// GEMM row (t, n) maps to scrambled node u = (t*1024+n)/3, s-block b = (t*1024+n)%3,
// feat column k maps to (h = k/64, f = k%64), s = b*64 + f.
__global__ __launch_bounds__(128) void k_feat(const float* __restrict__ nf,
                                              const float* __restrict__ fc,
                                              const float* __restrict__ attn_src,
                                              const float* __restrict__ attn_dst) {
    int n0 = blockIdx.x * 32;
    int t  = blockIdx.y;
    int c  = blockIdx.z;
    __shared__ __align__(16) float As2[16 * 64 * 2];   // [rp][i][pair]  8KB
    __shared__ float s_md[12];

    int tid = threadIdx.x;
    int u_base = (t * 1024 + n0) / 3;
    if (tid < 12) {
        int uu = u_base + tid; if (uu > N_ - 1) uu = N_ - 1;
        s_md[tid] = g_mdst[c * N_ + uu];
    }

    // stage interleaved row pairs: As2[(rp*64+i)*2] = {row rp, row rp+16}
    #pragma unroll
    for (int l = 0; l < 2; ++l) {
        int w = tid + l * 128;              // 0..255 = (rp, i4)
        int rp = w >> 4, i4 = w & 15;
        const float* base = nf + ((size_t)(c * N_ + n0 + rp) * T_ + t) * INF_ + i4 * 4;
        float4 lo = *reinterpret_cast<const float4*>(base);
        float4 hi = *reinterpret_cast<const float4*>(base + 16 * T_ * INF_);
        float4* d = reinterpret_cast<float4*>(As2 + (rp * 64 + i4 * 4) * 2);
        d[0] = make_float4(lo.x, hi.x, lo.y, hi.y);
        d[1] = make_float4(lo.z, hi.z, lo.w, hi.w);
    }
    __syncthreads();

    int k = tid;                            // 0..127 ; second col = k+128
    const float* fp0 = fc + (size_t)t * INF_ * K_ + k;

    ull acc[16][2];
    #pragma unroll
    for (int rp = 0; rp < 16; ++rp) { acc[rp][0] = 0ull; acc[rp][1] = 0ull; }

    for (int i4 = 0; i4 < 16; ++i4) {
        ull bb[4][2];
        #pragma unroll
        for (int j = 0; j < 4; ++j) {
            int i = i4 * 4 + j;
            bb[j][0] = dup2(fp0[i * K_]);
            bb[j][1] = dup2(fp0[i * K_ + 128]);
        }
        #pragma unroll
        for (int rp = 0; rp < 16; ++rp) {
            const ulonglong2* ap =
                reinterpret_cast<const ulonglong2*>(As2 + (rp * 64 + i4 * 4) * 2);
            ulonglong2 q0 = ap[0];
            ulonglong2 q1 = ap[1];
            acc[rp][0] = fma2(q0.x, bb[0][0], acc[rp][0]);
            acc[rp][1] = fma2(q0.x, bb[0][1], acc[rp][1]);
            acc[rp][0] = fma2(q0.y, bb[1][0], acc[rp][0]);
            acc[rp][1] = fma2(q0.y, bb[1][1], acc[rp][1]);
            acc[rp][0] = fma2(q1.x, bb[2][0], acc[rp][0]);
            acc[rp][1] = fma2(q1.x, bb[2][1], acc[rp][1]);
            acc[rp][0] = fma2(q1.y, bb[3][0], acc[rp][0]);
            acc[rp][1] = fma2(q1.y, bb[3][1], acc[rp][1]);
        }
    }

    // epilogue with permute scramble
    int h  = k >> 6, f = k & 63;
    int h2 = h + 2;
    int lane = tid & 31;
    float as0[3], ad0[3], as1[3], ad1[3];
    #pragma unroll
    for (int b = 0; b < 3; ++b) {
        as0[b] = attn_src[h  * S_ + b * 64 + f];
        ad0[b] = attn_dst[h  * S_ + b * 64 + f];
        as1[b] = attn_src[h2 * S_ + b * 64 + f];
        ad1[b] = attn_dst[h2 * S_ + b * 64 + f];
    }

    #pragma unroll
    for (int rp = 0; rp < 16; ++rp) {
        float v00, v10, v01, v11;
        unpack2(acc[rp][0], v00, v10);      // (row rp, h), (row rp+16, h)
        unpack2(acc[rp][1], v01, v11);      // (row rp, h2), (row rp+16, h2)

        int q_lo = t * 1024 + n0 + rp;
        int u_lo = q_lo / 3, b_lo = q_lo - u_lo * 3;
        int q_hi = q_lo + 16;
        int u_hi = q_hi / 3, b_hi = q_hi - u_hi * 3;
        float md0 = s_md[u_lo - u_base];
        float md1 = s_md[u_hi - u_base];

        g_Fd[((size_t)(c * 4 + h)  * N_ + u_lo) * S_ + b_lo * 64 + f] = __float2half(v00 * md0);
        g_Fd[((size_t)(c * 4 + h)  * N_ + u_hi) * S_ + b_hi * 64 + f] = __float2half(v10 * md1);
        g_Fd[((size_t)(c * 4 + h2) * N_ + u_lo) * S_ + b_lo * 64 + f] = __float2half(v01 * md0);
        g_Fd[((size_t)(c * 4 + h2) * N_ + u_hi) * S_ + b_hi * 64 + f] = __float2half(v11 * md1);

        float r0 = clipf(v00 * sel3(as0[0], as0[1], as0[2], b_lo));
        float r1 = clipf(v10 * sel3(as0[0], as0[1], as0[2], b_hi));
        float r2 = clipf(v01 * sel3(as1[0], as1[1], as1[2], b_lo));
        float r3 = clipf(v11 * sel3(as1[0], as1[1], as1[2], b_hi));
        float r4 = clipf(v00 * sel3(ad0[0], ad0[1], ad0[2], b_lo));
        float r5 = clipf(v10 * sel3(ad0[0], ad0[1], ad0[2], b_hi));
        float r6 = clipf(v01 * sel3(ad1[0], ad1[1], ad1[2], b_lo));
        float r7 = clipf(v11 * sel3(ad1[0], ad1[1], ad1[2], b_hi));
        #pragma unroll
        for (int o = 16; o; o >>= 1) {
            r0 += __shfl_down_sync(0xffffffffu, r0, o);
            r1 += __shfl_down_sync(0xffffffffu, r1, o);
            r2 += __shfl_down_sync(0xffffffffu, r2, o);
            r3 += __shfl_down_sync(0xffffffffu, r3, o);
            r4 += __shfl_down_sync(0xffffffffu, r4, o);
            r5 += __shfl_down_sync(0xffffffffu, r5, o);
            r6 += __shfl_down_sync(0xffffffffu, r6, o);
            r7 += __shfl_down_sync(0xffffffffu, r7, o);
        }
        if (lane == 0) {
            int b0 = (c * N_ + u_lo) * H_;
            int b1 = (c * N_ + u_hi) * H_;
            atomicAdd(&g_asrc[b0 + h],  r0);
            atomicAdd(&g_asrc[b1 + h],  r1);
            atomicAdd(&g_asrc[b0 + h2], r2);
            atomicAdd(&g_asrc[b1 + h2], r3);
            atomicAdd(&g_adst[b0 + h],  r4);
            atomicAdd(&g_adst[b1 + h],  r5);
            atomicAdd(&g_adst[b0 + h2], r6);
            atomicAdd(&g_adst[b1 + h2], r7);
        }
    }
}

// ---------------- K4: softmax over c -> a (fp32) + At (fp16 transposed) ----------------
__global__ __launch_bounds__(256) void k_attn_a(float* __restrict__ a_out) {
    int v = blockIdx.y;
    int u = blockIdx.x * 256 + threadIdx.x;
    __shared__ float s_asrc[32];
    if (threadIdx.x < 32) {
        int c = threadIdx.x >> 2, h = threadIdx.x & 3;
        s_asrc[threadIdx.x] = g_asrc[(c * N_ + v) * H_ + h] * g_msrc[c * N_ + v];
    }
    __syncthreads();

    float e[8][4];
    float den[4] = {0.f, 0.f, 0.f, 0.f};
    #pragma unroll
    for (int c = 0; c < 8; ++c) {
        float md = g_mdst[c * N_ + u];
        float4 d = *reinterpret_cast<const float4*>(&g_adst[(c * N_ + u) * H_]);
        float zd[4] = {d.x * md, d.y * md, d.z * md, d.w * md};
        #pragma unroll
        for (int h = 0; h < 4; ++h) {
            float z = s_asrc[c * 4 + h] + zd[h];
            z = (z >= 0.f) ? z : 0.2f * z;
            z = clipf(z);
            float ee = fexp(z);
            e[c][h] = ee;
            den[h] += ee;
        }
    }
    float inv[4];
    #pragma unroll
    for (int h = 0; h < 4; ++h) inv[h] = 1.0f / den[h];

    #pragma unroll
    for (int c = 0; c < 8; ++c) {
        float a0 = e[c][0] * inv[0];
        float a1 = e[c][1] * inv[1];
        float a2 = e[c][2] * inv[2];
        float a3 = e[c][3] * inv[3];
        reinterpret_cast<float4*>(a_out)[(size_t)(c * N_ + v) * N_ + u] =
            make_float4(a0, a1, a2, a3);
        g_At[((size_t)(c * 4 + 0) * N_ + v) * N_ + u] = __float2half(a0);
        g_At[((size_t)(c * 4 + 1) * N_ + v) * N_ + u] = __float2half(a1);
        g_At[((size_t)(c * 4 + 2) * N_ + v) * N_ + u] = __float2half(a2);
        g_At[((size_t)(c * 4 + 3) * N_ + v) * N_ + u] = __float2half(a3);
    }
}

// ---------------- K5: m = A @ Fd per (c,h); mma.sync + ldmatrix + reg double-buffer ----------------
#define LDA 72
#define LDB 200
__global__ __launch_bounds__(256) void k_m(float* __restrict__ outs) {
    __shared__ __align__(16) __half a_s[64 * LDA];
    __shared__ __align__(16) __half b_s[64 * LDB];

    int ch = blockIdx.y;
    int c  = ch >> 2;
    int v0 = blockIdx.x * 64;
    int tid = threadIdx.x;
    int lane = tid & 31, wid = tid >> 5;
    int wv = wid >> 2, wf = wid & 3;
    int g  = lane >> 2;
    int t2 = (lane & 3) * 2;

    const __half* Ag = g_At + (size_t)ch * N_ * N_ + (size_t)v0 * N_;
    const __half* Bg = g_Fd + (size_t)ch * N_ * S_;

    float acc[2][6][4];
    #pragma unroll
    for (int mi = 0; mi < 2; ++mi)
        #pragma unroll
        for (int ni = 0; ni < 6; ++ni)
            #pragma unroll
            for (int q = 0; q < 4; ++q) acc[mi][ni][q] = 0.f;

    int r = tid >> 2, seg = tid & 3;

    int4 av0 = reinterpret_cast<const int4*>(Ag + (size_t)r * N_ + seg * 16)[0];
    int4 av1 = reinterpret_cast<const int4*>(Ag + (size_t)r * N_ + seg * 16)[1];
    int4 bv[6];
    {
        const int4* bp = reinterpret_cast<const int4*>(Bg + (size_t)r * S_ + seg * 48);
        #pragma unroll
        for (int j = 0; j < 6; ++j) bv[j] = bp[j];
    }

    for (int u0 = 0; u0 < N_; u0 += 64) {
        int4* ad = reinterpret_cast<int4*>(a_s + r * LDA + seg * 16);
        ad[0] = av0; ad[1] = av1;
        int4* bd = reinterpret_cast<int4*>(b_s + r * LDB + seg * 48);
        #pragma unroll
        for (int j = 0; j < 6; ++j) bd[j] = bv[j];
        __syncthreads();

        if (u0 + 64 < N_) {
            const int4* ap = reinterpret_cast<const int4*>(Ag + (size_t)r * N_ + u0 + 64 + seg * 16);
            av0 = ap[0]; av1 = ap[1];
            const int4* bp = reinterpret_cast<const int4*>(Bg + (size_t)(u0 + 64 + r) * S_ + seg * 48);
            #pragma unroll
            for (int j = 0; j < 6; ++j) bv[j] = bp[j];
        }

        #pragma unroll
        for (int ki = 0; ki < 4; ++ki) {
            int k0 = ki * 16;
            uint32_t af[2][4];
            #pragma unroll
            for (int mi = 0; mi < 2; ++mi) {
                int row = wv * 32 + mi * 16 + (lane & 15);
                int col = k0 + ((lane >> 4) << 3);
                uint32_t addr = smem_u32(a_s + row * LDA + col);
                asm volatile("ldmatrix.sync.aligned.m8n8.x4.shared.b16 {%0,%1,%2,%3}, [%4];"
                             : "=r"(af[mi][0]), "=r"(af[mi][1]), "=r"(af[mi][2]), "=r"(af[mi][3])
                             : "r"(addr));
            }
            #pragma unroll
            for (int ni = 0; ni < 6; ++ni) {
                int krow = k0 + (lane & 15);
                int ncol = wf * 48 + ni * 8;
                uint32_t addr = smem_u32(b_s + krow * LDB + ncol);
                uint32_t b0, b1;
                asm volatile("ldmatrix.sync.aligned.m8n8.x2.trans.shared.b16 {%0,%1}, [%2];"
                             : "=r"(b0), "=r"(b1) : "r"(addr));
                #pragma unroll
                for (int mi = 0; mi < 2; ++mi) {
                    asm volatile(
                        "mma.sync.aligned.m16n8k16.row.col.f32.f16.f16.f32 "
                        "{%0,%1,%2,%3},{%4,%5,%6,%7},{%8,%9},{%0,%1,%2,%3};"
                        : "+f"(acc[mi][ni][0]), "+f"(acc[mi][ni][1]),
                          "+f"(acc[mi][ni][2]), "+f"(acc[mi][ni][3])
                        : "r"(af[mi][0]), "r"(af[mi][1]), "r"(af[mi][2]), "r"(af[mi][3]),
                          "r"(b0), "r"(b1));
                }
            }
        }
        __syncthreads();
    }

    #pragma unroll
    for (int mi = 0; mi < 2; ++mi) {
        #pragma unroll
        for (int ni = 0; ni < 6; ++ni) {
            int v = v0 + wv * 32 + mi * 16 + g;
            int f = wf * 48 + ni * 8 + t2;
            float* o0 = outs + (size_t)(c * N_ + v) * S_ + f;
            atomicAdd(o0,     fmaxf(acc[mi][ni][0], 0.f));
            atomicAdd(o0 + 1, fmaxf(acc[mi][ni][1], 0.f));
            float* o1 = outs + (size_t)(c * N_ + v + 8) * S_ + f;
            atomicAdd(o1,     fmaxf(acc[mi][ni][2], 0.f));
            atomicAdd(o1 + 1, fmaxf(acc[mi][ni][3], 0.f));
        }
    }
}

// ---------------- launch ----------------
extern "C" void kernel_launch(void* const* d_in, const int* in_sizes, int n_in,
                              void* d_out, int out_size) {
    const int*   edge = (const int*)d_in[0];
    const float* nf   = (const float*)d_in[1];
    const float* fc   = (const float*)d_in[2];
    const float* asv  = (const float*)d_in[3];
    const float* adv  = (const float*)d_in[4];

    float* outs  = (float*)d_out;                          // (8,1024,3,64)
    float* a_out = outs + (size_t)C_ * N_ * T_ * F_;       // (8,1024,1024,4)

    k_zero_outs<<<(C_ * N_ * T_ * F_ / 4) / 256, 256>>>(outs);
    k_zero_scratch<<<128, 256>>>();
    k_scatter<<<E_ / 256, 256>>>(edge);
    k_feat<<<dim3(32, 3, 8), 128>>>(nf, fc, asv, adv);
    k_attn_a<<<dim3(4, N_), 256>>>(a_out);
    k_m<<<dim3(16, 32), 256>>>(outs);
}

// round 7
// speedup vs baseline: 1.1803x; 1.0128x over previous
#include <cuda_runtime.h>
#include <cuda_fp16.h>
#include <cstdint>

#define C_   8
#define N_   1024
#define T_   3
#define INF_ 64
#define H_   4
#define F_   64
#define K_   256      // H*F
#define S_   192      // T*F
#define E_   65536
#define CN_  8192

typedef unsigned long long ull;

// ---------------- scratch ----------------
__device__ __align__(16) float  g_msrc[CN_];
__device__ __align__(16) float  g_mdst[CN_];
__device__ __align__(16) float  g_asrc[C_*N_*H_];          // RAW (pre-msrc)
__device__ __align__(16) float  g_adst[C_*N_*H_];          // RAW (pre-mdst)
__device__ __align__(16) float  g_wsrc[T_*3*H_*64];        // [t][b][h][i]
__device__ __align__(16) float  g_wdst[T_*3*H_*64];
__device__ __align__(16) __half g_Fd[(size_t)C_*H_*N_*S_]; // [c*4+h][u][s]  12.6MB
__device__ __align__(16) __half g_At[(size_t)C_*H_*N_*N_]; // [c*4+h][v][u]  67MB

// ---------------- helpers ----------------
__device__ __forceinline__ float clipf(float x) {
    return fminf(fmaxf(x, -1e9f), 1e9f);
}
__device__ __forceinline__ float fexp(float x) {
    float y  = x * 1.4426950408889634f;
    int   ni = __float2int_rn(y);
    float f  = y - (float)ni;
    float p  = 1.5403530393381608e-4f;
    p = fmaf(p, f, 1.3333558146428443e-3f);
    p = fmaf(p, f, 9.6181291076284770e-3f);
    p = fmaf(p, f, 5.5504108664821580e-2f);
    p = fmaf(p, f, 2.4022650695910071e-1f);
    p = fmaf(p, f, 6.9314718055994531e-1f);
    p = fmaf(p, f, 1.0f);
    return __int_as_float((ni + 127) << 23) * p;
}
__device__ __forceinline__ uint32_t smem_u32(const void* p) {
    return (uint32_t)__cvta_generic_to_shared(p);
}
__device__ __forceinline__ ull fma2(ull a, ull b, ull c) {
    ull d; asm("fma.rn.f32x2 %0, %1, %2, %3;" : "=l"(d) : "l"(a), "l"(b), "l"(c));
    return d;
}
__device__ __forceinline__ ull dup2(float x) {
    ull d; asm("mov.b64 %0, {%1,%1};" : "=l"(d) : "f"(x)); return d;
}
__device__ __forceinline__ void unpack2(ull v, float& lo, float& hi) {
    asm("mov.b64 {%0,%1}, %2;" : "=f"(lo), "=f"(hi) : "l"(v));
}

// ---------------- K0a: zero masks ----------------
__global__ __launch_bounds__(256) void k_zero_masks() {
    int i = blockIdx.x * 256 + threadIdx.x;
    if (i < CN_) { g_msrc[i] = 0.f; g_mdst[i] = 0.f; }
}
// ---------------- K0b: zero outs ----------------
__global__ __launch_bounds__(256) void k_zero_outs(float* __restrict__ outs) {
    int i = blockIdx.x * 256 + threadIdx.x;
    reinterpret_cast<float4*>(outs)[i] = make_float4(0.f, 0.f, 0.f, 0.f);
}
// ---------------- K1: scatter edge masks (int32) ----------------
__global__ __launch_bounds__(256) void k_scatter(const int* __restrict__ edge) {
    int i = blockIdx.x * 256 + threadIdx.x;
    if (i < E_) {
        g_msrc[edge[i]      & (CN_ - 1)] = 1.f;
        g_mdst[edge[E_ + i] & (CN_ - 1)] = 1.f;
    }
}

// ---------------- Kw: precompute w_src/w_dst [t][b][h][i] ----------------
// w[t,b,h,i] = sum_f fc[t,i,h*64+f] * attn[h, b*64+f]   (clip is a numeric no-op)
__global__ __launch_bounds__(256) void k_w(const float* __restrict__ fc,
                                           const float* __restrict__ asv,
                                           const float* __restrict__ adv) {
    int t = blockIdx.x, b = blockIdx.y;
    int h = threadIdx.x >> 6, i = threadIdx.x & 63;
    const float* fp = fc + ((size_t)t * INF_ + i) * K_ + h * 64;
    const float* ap = asv + h * S_ + b * 64;
    const float* dp = adv + h * S_ + b * 64;
    float ws = 0.f, wd = 0.f;
    #pragma unroll 8
    for (int f = 0; f < 64; ++f) {
        float v = fp[f];
        ws = fmaf(v, ap[f], ws);
        wd = fmaf(v, dp[f], wd);
    }
    int o = ((t * 3 + b) * 4 + h) * 64 + i;
    g_wsrc[o] = ws;
    g_wdst[o] = wd;
}

// ---------------- Kav: a_src/a_dst directly from node_feats ----------------
// one warp per (c,u): a[c,u,h] = sum_b sum_i hs[c,n(u,b),t(u,b),i] * w[t,b,h,i]
__global__ __launch_bounds__(256) void k_av(const float* __restrict__ nf) {
    int W    = blockIdx.x * 8 + (threadIdx.x >> 5);
    int lane = threadIdx.x & 31;
    int c = W >> 10, u = W & 1023;

    float as[4] = {0.f, 0.f, 0.f, 0.f};
    float ad[4] = {0.f, 0.f, 0.f, 0.f};
    #pragma unroll
    for (int b = 0; b < 3; ++b) {
        int q = 3 * u + b, t = q >> 10, n = q & 1023;
        const float* row = nf + ((size_t)(c * N_ + n) * T_ + t) * INF_;
        float x0 = row[lane], x1 = row[lane + 32];
        const float* ws = g_wsrc + ((t * 3 + b) * 4) * 64;
        const float* wd = g_wdst + ((t * 3 + b) * 4) * 64;
        #pragma unroll
        for (int h = 0; h < 4; ++h) {
            as[h] = fmaf(x0, ws[h * 64 + lane], as[h]);
            as[h] = fmaf(x1, ws[h * 64 + lane + 32], as[h]);
            ad[h] = fmaf(x0, wd[h * 64 + lane], ad[h]);
            ad[h] = fmaf(x1, wd[h * 64 + lane + 32], ad[h]);
        }
    }
    #pragma unroll
    for (int o = 16; o; o >>= 1) {
        #pragma unroll
        for (int h = 0; h < 4; ++h) {
            as[h] += __shfl_xor_sync(0xffffffffu, as[h], o);
            ad[h] += __shfl_xor_sync(0xffffffffu, ad[h], o);
        }
    }
    if (lane == 0) {
        int base = (c * N_ + u) * H_;
        *reinterpret_cast<float4*>(&g_asrc[base]) = make_float4(as[0], as[1], as[2], as[3]);
        *reinterpret_cast<float4*>(&g_adst[base]) = make_float4(ad[0], ad[1], ad[2], ad[3]);
    }
}

// ---------------- K2: feat GEMM (f32x2) + scrambled Fd write only ----------------
// GEMM row (t,n) -> u=(t*1024+n)/3, b=(t*1024+n)%3; col k -> (h=k/64, f=k%64); s=b*64+f
__global__ __launch_bounds__(128) void k_feat(const float* __restrict__ nf,
                                              const float* __restrict__ fc) {
    int n0 = blockIdx.x * 32;
    int t  = blockIdx.y;
    int c  = blockIdx.z;
    __shared__ __align__(16) float As2[16 * 64 * 2];   // [rp][i][pair]  8KB
    __shared__ float s_md[12];

    int tid = threadIdx.x;
    int u_base = (t * 1024 + n0) / 3;
    if (tid < 12) {
        int uu = u_base + tid; if (uu > N_ - 1) uu = N_ - 1;
        s_md[tid] = g_mdst[c * N_ + uu];
    }

    #pragma unroll
    for (int l = 0; l < 2; ++l) {
        int w = tid + l * 128;              // 0..255 = (rp, i4)
        int rp = w >> 4, i4 = w & 15;
        const float* base = nf + ((size_t)(c * N_ + n0 + rp) * T_ + t) * INF_ + i4 * 4;
        float4 lo = *reinterpret_cast<const float4*>(base);
        float4 hi = *reinterpret_cast<const float4*>(base + 16 * T_ * INF_);
        float4* d = reinterpret_cast<float4*>(As2 + (rp * 64 + i4 * 4) * 2);
        d[0] = make_float4(lo.x, hi.x, lo.y, hi.y);
        d[1] = make_float4(lo.z, hi.z, lo.w, hi.w);
    }
    __syncthreads();

    int k = tid;                            // 0..127 ; second col = k+128
    const float* fp0 = fc + (size_t)t * INF_ * K_ + k;

    ull acc[16][2];
    #pragma unroll
    for (int rp = 0; rp < 16; ++rp) { acc[rp][0] = 0ull; acc[rp][1] = 0ull; }

    for (int i4 = 0; i4 < 16; ++i4) {
        ull bb[4][2];
        #pragma unroll
        for (int j = 0; j < 4; ++j) {
            int i = i4 * 4 + j;
            bb[j][0] = dup2(fp0[i * K_]);
            bb[j][1] = dup2(fp0[i * K_ + 128]);
        }
        #pragma unroll
        for (int rp = 0; rp < 16; ++rp) {
            const ulonglong2* ap =
                reinterpret_cast<const ulonglong2*>(As2 + (rp * 64 + i4 * 4) * 2);
            ulonglong2 q0 = ap[0];
            ulonglong2 q1 = ap[1];
            acc[rp][0] = fma2(q0.x, bb[0][0], acc[rp][0]);
            acc[rp][1] = fma2(q0.x, bb[0][1], acc[rp][1]);
            acc[rp][0] = fma2(q0.y, bb[1][0], acc[rp][0]);
            acc[rp][1] = fma2(q0.y, bb[1][1], acc[rp][1]);
            acc[rp][0] = fma2(q1.x, bb[2][0], acc[rp][0]);
            acc[rp][1] = fma2(q1.x, bb[2][1], acc[rp][1]);
            acc[rp][0] = fma2(q1.y, bb[3][0], acc[rp][0]);
            acc[rp][1] = fma2(q1.y, bb[3][1], acc[rp][1]);
        }
    }

    // epilogue: scrambled Fd stores only
    int h  = k >> 6, f = k & 63;
    int h2 = h + 2;
    #pragma unroll
    for (int rp = 0; rp < 16; ++rp) {
        float v00, v10, v01, v11;
        unpack2(acc[rp][0], v00, v10);      // (row rp, h), (row rp+16, h)
        unpack2(acc[rp][1], v01, v11);      // (row rp, h2), (row rp+16, h2)

        int q_lo = t * 1024 + n0 + rp;
        int u_lo = q_lo / 3, b_lo = q_lo - u_lo * 3;
        int q_hi = q_lo + 16;
        int u_hi = q_hi / 3, b_hi = q_hi - u_hi * 3;
        float md0 = s_md[u_lo - u_base];
        float md1 = s_md[u_hi - u_base];

        g_Fd[((size_t)(c * 4 + h)  * N_ + u_lo) * S_ + b_lo * 64 + f] = __float2half(v00 * md0);
        g_Fd[((size_t)(c * 4 + h)  * N_ + u_hi) * S_ + b_hi * 64 + f] = __float2half(v10 * md1);
        g_Fd[((size_t)(c * 4 + h2) * N_ + u_lo) * S_ + b_lo * 64 + f] = __float2half(v01 * md0);
        g_Fd[((size_t)(c * 4 + h2) * N_ + u_hi) * S_ + b_hi * 64 + f] = __float2half(v11 * md1);
    }
}

// ---------------- K4: softmax over c -> a (fp32) + At (fp16 transposed) ----------------
__global__ __launch_bounds__(256) void k_attn_a(float* __restrict__ a_out) {
    int v = blockIdx.y;
    int u = blockIdx.x * 256 + threadIdx.x;
    __shared__ float s_asrc[32];
    if (threadIdx.x < 32) {
        int c = threadIdx.x >> 2, h = threadIdx.x & 3;
        s_asrc[threadIdx.x] = g_asrc[(c * N_ + v) * H_ + h] * g_msrc[c * N_ + v];
    }
    __syncthreads();

    float e[8][4];
    float den[4] = {0.f, 0.f, 0.f, 0.f};
    #pragma unroll
    for (int c = 0; c < 8; ++c) {
        float md = g_mdst[c * N_ + u];
        float4 d = *reinterpret_cast<const float4*>(&g_adst[(c * N_ + u) * H_]);
        float zd[4] = {d.x * md, d.y * md, d.z * md, d.w * md};
        #pragma unroll
        for (int h = 0; h < 4; ++h) {
            float z = s_asrc[c * 4 + h] + zd[h];
            z = (z >= 0.f) ? z : 0.2f * z;
            z = clipf(z);
            float ee = fexp(z);
            e[c][h] = ee;
            den[h] += ee;
        }
    }
    float inv[4];
    #pragma unroll
    for (int h = 0; h < 4; ++h) inv[h] = 1.0f / den[h];

    #pragma unroll
    for (int c = 0; c < 8; ++c) {
        float a0 = e[c][0] * inv[0];
        float a1 = e[c][1] * inv[1];
        float a2 = e[c][2] * inv[2];
        float a3 = e[c][3] * inv[3];
        reinterpret_cast<float4*>(a_out)[(size_t)(c * N_ + v) * N_ + u] =
            make_float4(a0, a1, a2, a3);
        g_At[((size_t)(c * 4 + 0) * N_ + v) * N_ + u] = __float2half(a0);
        g_At[((size_t)(c * 4 + 1) * N_ + v) * N_ + u] = __float2half(a1);
        g_At[((size_t)(c * 4 + 2) * N_ + v) * N_ + u] = __float2half(a2);
        g_At[((size_t)(c * 4 + 3) * N_ + v) * N_ + u] = __float2half(a3);
    }
}

// ---------------- K5: m = A @ Fd per (c,h); 128-row tiles, mma.sync + ldmatrix ----------------
#define LDA 72
#define LDB 200
__global__ __launch_bounds__(256) void k_m(float* __restrict__ outs) {
    __shared__ __align__(16) __half a_s[128 * LDA];    // 18.4KB
    __shared__ __align__(16) __half b_s[64 * LDB];     // 25.6KB

    int ch = blockIdx.y;
    int c  = ch >> 2;
    int v0 = blockIdx.x * 128;
    int tid = threadIdx.x;
    int lane = tid & 31, wid = tid >> 5;
    int wv = wid >> 2, wf = wid & 3;    // wv 0..1 (64 rows each), wf 0..3 (48 cols each)
    int g  = lane >> 2;
    int t2 = (lane & 3) * 2;

    const __half* Ag = g_At + (size_t)ch * N_ * N_ + (size_t)v0 * N_;
    const __half* Bg = g_Fd + (size_t)ch * N_ * S_;

    float acc[4][6][4];
    #pragma unroll
    for (int mi = 0; mi < 4; ++mi)
        #pragma unroll
        for (int ni = 0; ni < 6; ++ni)
            #pragma unroll
            for (int q = 0; q < 4; ++q) acc[mi][ni][q] = 0.f;

    int r2 = tid >> 1, sg2 = tid & 1;   // A staging: 128 rows x 2 threads, 32 halfs each
    int r4 = tid >> 2, sg4 = tid & 3;   // B staging: 64 rows x 4 threads, 48 halfs each

    // prologue (u0 = 0)
    int4 av[4];
    {
        const int4* ap = reinterpret_cast<const int4*>(Ag + (size_t)r2 * N_ + sg2 * 32);
        #pragma unroll
        for (int j = 0; j < 4; ++j) av[j] = ap[j];
    }
    int4 bv[6];
    {
        const int4* bp = reinterpret_cast<const int4*>(Bg + (size_t)r4 * S_ + sg4 * 48);
        #pragma unroll
        for (int j = 0; j < 6; ++j) bv[j] = bp[j];
    }

    for (int u0 = 0; u0 < N_; u0 += 64) {
        int4* ad = reinterpret_cast<int4*>(a_s + r2 * LDA + sg2 * 32);
        #pragma unroll
        for (int j = 0; j < 4; ++j) ad[j] = av[j];
        int4* bd = reinterpret_cast<int4*>(b_s + r4 * LDB + sg4 * 48);
        #pragma unroll
        for (int j = 0; j < 6; ++j) bd[j] = bv[j];
        __syncthreads();

        if (u0 + 64 < N_) {
            const int4* ap = reinterpret_cast<const int4*>(Ag + (size_t)r2 * N_ + u0 + 64 + sg2 * 32);
            #pragma unroll
            for (int j = 0; j < 4; ++j) av[j] = ap[j];
            const int4* bp = reinterpret_cast<const int4*>(Bg + (size_t)(u0 + 64 + r4) * S_ + sg4 * 48);
            #pragma unroll
            for (int j = 0; j < 6; ++j) bv[j] = bp[j];
        }

        #pragma unroll
        for (int ki = 0; ki < 4; ++ki) {
            int k0 = ki * 16;
            uint32_t af[4][4];
            #pragma unroll
            for (int mi = 0; mi < 4; ++mi) {
                int row = wv * 64 + mi * 16 + (lane & 15);
                int col = k0 + ((lane >> 4) << 3);
                uint32_t addr = smem_u32(a_s + row * LDA + col);
                asm volatile("ldmatrix.sync.aligned.m8n8.x4.shared.b16 {%0,%1,%2,%3}, [%4];"
                             : "=r"(af[mi][0]), "=r"(af[mi][1]), "=r"(af[mi][2]), "=r"(af[mi][3])
                             : "r"(addr));
            }
            #pragma unroll
            for (int ni = 0; ni < 6; ++ni) {
                int krow = k0 + (lane & 15);
                int ncol = wf * 48 + ni * 8;
                uint32_t addr = smem_u32(b_s + krow * LDB + ncol);
                uint32_t b0, b1;
                asm volatile("ldmatrix.sync.aligned.m8n8.x2.trans.shared.b16 {%0,%1}, [%2];"
                             : "=r"(b0), "=r"(b1) : "r"(addr));
                #pragma unroll
                for (int mi = 0; mi < 4; ++mi) {
                    asm volatile(
                        "mma.sync.aligned.m16n8k16.row.col.f32.f16.f16.f32 "
                        "{%0,%1,%2,%3},{%4,%5,%6,%7},{%8,%9},{%0,%1,%2,%3};"
                        : "+f"(acc[mi][ni][0]), "+f"(acc[mi][ni][1]),
                          "+f"(acc[mi][ni][2]), "+f"(acc[mi][ni][3])
                        : "r"(af[mi][0]), "r"(af[mi][1]), "r"(af[mi][2]), "r"(af[mi][3]),
                          "r"(b0), "r"(b1));
                }
            }
        }
        __syncthreads();
    }

    #pragma unroll
    for (int mi = 0; mi < 4; ++mi) {
        #pragma unroll
        for (int ni = 0; ni < 6; ++ni) {
            int v = v0 + wv * 64 + mi * 16 + g;
            int f = wf * 48 + ni * 8 + t2;
            float* o0 = outs + (size_t)(c * N_ + v) * S_ + f;
            atomicAdd(o0,     fmaxf(acc[mi][ni][0], 0.f));
            atomicAdd(o0 + 1, fmaxf(acc[mi][ni][1], 0.f));
            float* o1 = outs + (size_t)(c * N_ + v + 8) * S_ + f;
            atomicAdd(o1,     fmaxf(acc[mi][ni][2], 0.f));
            atomicAdd(o1 + 1, fmaxf(acc[mi][ni][3], 0.f));
        }
    }
}

// ---------------- launch ----------------
extern "C" void kernel_launch(void* const* d_in, const int* in_sizes, int n_in,
                              void* d_out, int out_size) {
    const int*   edge = (const int*)d_in[0];
    const float* nf   = (const float*)d_in[1];
    const float* fc   = (const float*)d_in[2];
    const float* asv  = (const float*)d_in[3];
    const float* adv  = (const float*)d_in[4];

    float* outs  = (float*)d_out;                          // (8,1024,3,64)
    float* a_out = outs + (size_t)C_ * N_ * T_ * F_;       // (8,1024,1024,4)

    k_zero_outs<<<(C_ * N_ * T_ * F_ / 4) / 256, 256>>>(outs);
    k_zero_masks<<<32, 256>>>();
    k_scatter<<<E_ / 256, 256>>>(edge);
    k_w<<<dim3(3, 3), 256>>>(fc, asv, adv);
    k_av<<<1024, 256>>>(nf);
    k_feat<<<dim3(32, 3, 8), 128>>>(nf, fc);
    k_attn_a<<<dim3(4, N_), 256>>>(a_out);
    k_m<<<dim3(8, 32), 256>>>(outs);
}

// round 8
// speedup vs baseline: 1.2505x; 1.0595x over previous
#include <cuda_runtime.h>
#include <cuda_fp16.h>
#include <cstdint>

#define C_   8
#define N_   1024
#define T_   3
#define INF_ 64
#define H_   4
#define F_   64
#define K_   256      // H*F
#define S_   192      // T*F
#define E_   65536
#define CN_  8192

typedef unsigned long long ull;

// ---------------- scratch ----------------
__device__ __align__(16) float  g_msrc[CN_];
__device__ __align__(16) float  g_mdst[CN_];
__device__ __align__(16) float  g_asrc[C_*N_*H_];          // RAW (pre-msrc)
__device__ __align__(16) float  g_adst[C_*N_*H_];          // RAW (pre-mdst)
__device__ __align__(16) float  g_wsrc[T_*3*H_*64];        // [t][b][h][i]
__device__ __align__(16) float  g_wdst[T_*3*H_*64];
__device__ __align__(16) __half g_Fd[(size_t)C_*H_*N_*S_]; // [c*4+h][u][s]  12.6MB
__device__ __align__(16) __half g_At[(size_t)C_*H_*N_*N_]; // [c*4+h][v][u]  67MB

// ---------------- helpers ----------------
__device__ __forceinline__ float clipf(float x) {
    return fminf(fmaxf(x, -1e9f), 1e9f);
}
__device__ __forceinline__ float fexp(float x) {
    float y  = x * 1.4426950408889634f;
    int   ni = __float2int_rn(y);
    float f  = y - (float)ni;
    float p  = 1.5403530393381608e-4f;
    p = fmaf(p, f, 1.3333558146428443e-3f);
    p = fmaf(p, f, 9.6181291076284770e-3f);
    p = fmaf(p, f, 5.5504108664821580e-2f);
    p = fmaf(p, f, 2.4022650695910071e-1f);
    p = fmaf(p, f, 6.9314718055994531e-1f);
    p = fmaf(p, f, 1.0f);
    return __int_as_float((ni + 127) << 23) * p;
}
__device__ __forceinline__ uint32_t smem_u32(const void* p) {
    return (uint32_t)__cvta_generic_to_shared(p);
}
__device__ __forceinline__ ull fma2(ull a, ull b, ull c) {
    ull d; asm("fma.rn.f32x2 %0, %1, %2, %3;" : "=l"(d) : "l"(a), "l"(b), "l"(c));
    return d;
}
__device__ __forceinline__ ull dup2(float x) {
    ull d; asm("mov.b64 %0, {%1,%1};" : "=l"(d) : "f"(x)); return d;
}
__device__ __forceinline__ void unpack2(ull v, float& lo, float& hi) {
    asm("mov.b64 {%0,%1}, %2;" : "=f"(lo), "=f"(hi) : "l"(v));
}

// ---------------- K_prep: zero outs + zero masks + compute w ----------------
// blocks [0,1536): zero outs; [1536,1568): zero masks; [1568,1577): w[t][b]
__global__ __launch_bounds__(256) void k_prep(float* __restrict__ outs,
                                              const float* __restrict__ fc,
                                              const float* __restrict__ asv,
                                              const float* __restrict__ adv) {
    int blk = blockIdx.x;
    int tid = threadIdx.x;
    if (blk < 1536) {
        reinterpret_cast<float4*>(outs)[blk * 256 + tid] = make_float4(0.f, 0.f, 0.f, 0.f);
        return;
    }
    if (blk < 1568) {
        int i = (blk - 1536) * 256 + tid;
        g_msrc[i] = 0.f; g_mdst[i] = 0.f;
        return;
    }
    // w part: 9 blocks, one per (t,b)
    int w = blk - 1568;
    int t = w / 3, b = w - t * 3;
    __shared__ float s_a[256], s_d[256];
    {
        int hh = tid >> 6, ff = tid & 63;
        s_a[tid] = asv[hh * S_ + b * 64 + ff];
        s_d[tid] = adv[hh * S_ + b * 64 + ff];
    }
    __syncthreads();
    int h = tid >> 6, i = tid & 63;
    const float4* fp = reinterpret_cast<const float4*>(
        fc + ((size_t)t * INF_ + i) * K_ + h * 64);
    float4 v[16];
    #pragma unroll
    for (int j = 0; j < 16; ++j) v[j] = fp[j];       // 16 independent LDGs
    float ws = 0.f, wd = 0.f;
    #pragma unroll
    for (int j = 0; j < 16; ++j) {
        const float* sa = s_a + h * 64 + j * 4;
        const float* sd = s_d + h * 64 + j * 4;
        ws = fmaf(v[j].x, sa[0], ws); wd = fmaf(v[j].x, sd[0], wd);
        ws = fmaf(v[j].y, sa[1], ws); wd = fmaf(v[j].y, sd[1], wd);
        ws = fmaf(v[j].z, sa[2], ws); wd = fmaf(v[j].z, sd[2], wd);
        ws = fmaf(v[j].w, sa[3], ws); wd = fmaf(v[j].w, sd[3], wd);
    }
    int o = ((t * 3 + b) * 4 + h) * 64 + i;
    g_wsrc[o] = ws;
    g_wdst[o] = wd;
}

// ---------------- K1: scatter edge masks (int32) ----------------
__global__ __launch_bounds__(256) void k_scatter(const int* __restrict__ edge) {
    int i = blockIdx.x * 256 + threadIdx.x;
    if (i < E_) {
        g_msrc[edge[i]      & (CN_ - 1)] = 1.f;
        g_mdst[edge[E_ + i] & (CN_ - 1)] = 1.f;
    }
}

// ---------------- Kav: a_src/a_dst directly from node_feats ----------------
__global__ __launch_bounds__(256) void k_av(const float* __restrict__ nf) {
    int W    = blockIdx.x * 8 + (threadIdx.x >> 5);
    int lane = threadIdx.x & 31;
    int c = W >> 10, u = W & 1023;

    float as[4] = {0.f, 0.f, 0.f, 0.f};
    float ad[4] = {0.f, 0.f, 0.f, 0.f};
    #pragma unroll
    for (int b = 0; b < 3; ++b) {
        int q = 3 * u + b, t = q >> 10, n = q & 1023;
        const float* row = nf + ((size_t)(c * N_ + n) * T_ + t) * INF_;
        float x0 = row[lane], x1 = row[lane + 32];
        const float* ws = g_wsrc + ((t * 3 + b) * 4) * 64;
        const float* wd = g_wdst + ((t * 3 + b) * 4) * 64;
        #pragma unroll
        for (int h = 0; h < 4; ++h) {
            as[h] = fmaf(x0, ws[h * 64 + lane], as[h]);
            as[h] = fmaf(x1, ws[h * 64 + lane + 32], as[h]);
            ad[h] = fmaf(x0, wd[h * 64 + lane], ad[h]);
            ad[h] = fmaf(x1, wd[h * 64 + lane + 32], ad[h]);
        }
    }
    #pragma unroll
    for (int o = 16; o; o >>= 1) {
        #pragma unroll
        for (int h = 0; h < 4; ++h) {
            as[h] += __shfl_xor_sync(0xffffffffu, as[h], o);
            ad[h] += __shfl_xor_sync(0xffffffffu, ad[h], o);
        }
    }
    if (lane == 0) {
        int base = (c * N_ + u) * H_;
        *reinterpret_cast<float4*>(&g_asrc[base]) = make_float4(as[0], as[1], as[2], as[3]);
        *reinterpret_cast<float4*>(&g_adst[base]) = make_float4(ad[0], ad[1], ad[2], ad[3]);
    }
}

// ---------------- K2: feat GEMM (f32x2, pipelined b) + scrambled Fd write ----------------
__global__ __launch_bounds__(128) void k_feat(const float* __restrict__ nf,
                                              const float* __restrict__ fc) {
    int n0 = blockIdx.x * 32;
    int t  = blockIdx.y;
    int c  = blockIdx.z;
    __shared__ __align__(16) float As2[16 * 64 * 2];   // [rp][i][pair]  8KB
    __shared__ float s_md[12];

    int tid = threadIdx.x;
    int u_base = (t * 1024 + n0) / 3;
    if (tid < 12) {
        int uu = u_base + tid; if (uu > N_ - 1) uu = N_ - 1;
        s_md[tid] = g_mdst[c * N_ + uu];
    }

    #pragma unroll
    for (int l = 0; l < 2; ++l) {
        int w = tid + l * 128;              // 0..255 = (rp, i4)
        int rp = w >> 4, i4 = w & 15;
        const float* base = nf + ((size_t)(c * N_ + n0 + rp) * T_ + t) * INF_ + i4 * 4;
        float4 lo = *reinterpret_cast<const float4*>(base);
        float4 hi = *reinterpret_cast<const float4*>(base + 16 * T_ * INF_);
        float4* d = reinterpret_cast<float4*>(As2 + (rp * 64 + i4 * 4) * 2);
        d[0] = make_float4(lo.x, hi.x, lo.y, hi.y);
        d[1] = make_float4(lo.z, hi.z, lo.w, hi.w);
    }
    __syncthreads();

    int k = tid;                            // 0..127 ; second col = k+128
    const float* fp0 = fc + (size_t)t * INF_ * K_ + k;

    ull acc[16][2];
    #pragma unroll
    for (int rp = 0; rp < 16; ++rp) { acc[rp][0] = 0ull; acc[rp][1] = 0ull; }

    // software-pipelined b operands
    ull bb[4][2], bn[4][2];
    #pragma unroll
    for (int j = 0; j < 4; ++j) {
        bb[j][0] = dup2(fp0[j * K_]);
        bb[j][1] = dup2(fp0[j * K_ + 128]);
    }

    for (int i4 = 0; i4 < 16; ++i4) {
        if (i4 < 15) {
            #pragma unroll
            for (int j = 0; j < 4; ++j) {
                int i = (i4 + 1) * 4 + j;
                bn[j][0] = dup2(fp0[i * K_]);
                bn[j][1] = dup2(fp0[i * K_ + 128]);
            }
        }
        #pragma unroll
        for (int rp = 0; rp < 16; ++rp) {
            const ulonglong2* ap =
                reinterpret_cast<const ulonglong2*>(As2 + (rp * 64 + i4 * 4) * 2);
            ulonglong2 q0 = ap[0];
            ulonglong2 q1 = ap[1];
            acc[rp][0] = fma2(q0.x, bb[0][0], acc[rp][0]);
            acc[rp][1] = fma2(q0.x, bb[0][1], acc[rp][1]);
            acc[rp][0] = fma2(q0.y, bb[1][0], acc[rp][0]);
            acc[rp][1] = fma2(q0.y, bb[1][1], acc[rp][1]);
            acc[rp][0] = fma2(q1.x, bb[2][0], acc[rp][0]);
            acc[rp][1] = fma2(q1.x, bb[2][1], acc[rp][1]);
            acc[rp][0] = fma2(q1.y, bb[3][0], acc[rp][0]);
            acc[rp][1] = fma2(q1.y, bb[3][1], acc[rp][1]);
        }
        #pragma unroll
        for (int j = 0; j < 4; ++j) { bb[j][0] = bn[j][0]; bb[j][1] = bn[j][1]; }
    }

    // epilogue: scrambled Fd stores only
    int h  = k >> 6, f = k & 63;
    int h2 = h + 2;
    #pragma unroll
    for (int rp = 0; rp < 16; ++rp) {
        float v00, v10, v01, v11;
        unpack2(acc[rp][0], v00, v10);
        unpack2(acc[rp][1], v01, v11);

        int q_lo = t * 1024 + n0 + rp;
        int u_lo = q_lo / 3, b_lo = q_lo - u_lo * 3;
        int q_hi = q_lo + 16;
        int u_hi = q_hi / 3, b_hi = q_hi - u_hi * 3;
        float md0 = s_md[u_lo - u_base];
        float md1 = s_md[u_hi - u_base];

        g_Fd[((size_t)(c * 4 + h)  * N_ + u_lo) * S_ + b_lo * 64 + f] = __float2half(v00 * md0);
        g_Fd[((size_t)(c * 4 + h)  * N_ + u_hi) * S_ + b_hi * 64 + f] = __float2half(v10 * md1);
        g_Fd[((size_t)(c * 4 + h2) * N_ + u_lo) * S_ + b_lo * 64 + f] = __float2half(v01 * md0);
        g_Fd[((size_t)(c * 4 + h2) * N_ + u_hi) * S_ + b_hi * 64 + f] = __float2half(v11 * md1);
    }
}

// ---------------- K4: softmax over c -> a (fp32) + At (fp16 transposed) ----------------
__global__ __launch_bounds__(256) void k_attn_a(float* __restrict__ a_out) {
    int v = blockIdx.y;
    int u = blockIdx.x * 256 + threadIdx.x;
    __shared__ float s_asrc[32];
    if (threadIdx.x < 32) {
        int c = threadIdx.x >> 2, h = threadIdx.x & 3;
        s_asrc[threadIdx.x] = g_asrc[(c * N_ + v) * H_ + h] * g_msrc[c * N_ + v];
    }
    __syncthreads();

    float e[8][4];
    float den[4] = {0.f, 0.f, 0.f, 0.f};
    #pragma unroll
    for (int c = 0; c < 8; ++c) {
        float md = g_mdst[c * N_ + u];
        float4 d = *reinterpret_cast<const float4*>(&g_adst[(c * N_ + u) * H_]);
        float zd[4] = {d.x * md, d.y * md, d.z * md, d.w * md};
        #pragma unroll
        for (int h = 0; h < 4; ++h) {
            float z = s_asrc[c * 4 + h] + zd[h];
            z = (z >= 0.f) ? z : 0.2f * z;
            z = clipf(z);
            float ee = fexp(z);
            e[c][h] = ee;
            den[h] += ee;
        }
    }
    float inv[4];
    #pragma unroll
    for (int h = 0; h < 4; ++h) inv[h] = 1.0f / den[h];

    #pragma unroll
    for (int c = 0; c < 8; ++c) {
        float a0 = e[c][0] * inv[0];
        float a1 = e[c][1] * inv[1];
        float a2 = e[c][2] * inv[2];
        float a3 = e[c][3] * inv[3];
        reinterpret_cast<float4*>(a_out)[(size_t)(c * N_ + v) * N_ + u] =
            make_float4(a0, a1, a2, a3);
        g_At[((size_t)(c * 4 + 0) * N_ + v) * N_ + u] = __float2half(a0);
        g_At[((size_t)(c * 4 + 1) * N_ + v) * N_ + u] = __float2half(a1);
        g_At[((size_t)(c * 4 + 2) * N_ + v) * N_ + u] = __float2half(a2);
        g_At[((size_t)(c * 4 + 3) * N_ + v) * N_ + u] = __float2half(a3);
    }
}

// ---------------- K5: m = A @ Fd per (c,h); 128-row tiles, ldmatrix x4 ----------------
#define LDA 72
#define LDB 200
__global__ __launch_bounds__(256) void k_m(float* __restrict__ outs) {
    __shared__ __align__(16) __half a_s[128 * LDA];
    __shared__ __align__(16) __half b_s[64 * LDB];

    int ch = blockIdx.y;
    int c  = ch >> 2;
    int v0 = blockIdx.x * 128;
    int tid = threadIdx.x;
    int lane = tid & 31, wid = tid >> 5;
    int wv = wid >> 2, wf = wid & 3;
    int g  = lane >> 2;
    int t2 = (lane & 3) * 2;

    const __half* Ag = g_At + (size_t)ch * N_ * N_ + (size_t)v0 * N_;
    const __half* Bg = g_Fd + (size_t)ch * N_ * S_;

    float acc[4][6][4];
    #pragma unroll
    for (int mi = 0; mi < 4; ++mi)
        #pragma unroll
        for (int ni = 0; ni < 6; ++ni)
            #pragma unroll
            for (int q = 0; q < 4; ++q) acc[mi][ni][q] = 0.f;

    int r2 = tid >> 1, sg2 = tid & 1;
    int r4 = tid >> 2, sg4 = tid & 3;

    int4 av[4];
    {
        const int4* ap = reinterpret_cast<const int4*>(Ag + (size_t)r2 * N_ + sg2 * 32);
        #pragma unroll
        for (int j = 0; j < 4; ++j) av[j] = ap[j];
    }
    int4 bv[6];
    {
        const int4* bp = reinterpret_cast<const int4*>(Bg + (size_t)r4 * S_ + sg4 * 48);
        #pragma unroll
        for (int j = 0; j < 6; ++j) bv[j] = bp[j];
    }

    for (int u0 = 0; u0 < N_; u0 += 64) {
        int4* ad = reinterpret_cast<int4*>(a_s + r2 * LDA + sg2 * 32);
        #pragma unroll
        for (int j = 0; j < 4; ++j) ad[j] = av[j];
        int4* bd = reinterpret_cast<int4*>(b_s + r4 * LDB + sg4 * 48);
        #pragma unroll
        for (int j = 0; j < 6; ++j) bd[j] = bv[j];
        __syncthreads();

        if (u0 + 64 < N_) {
            const int4* ap = reinterpret_cast<const int4*>(Ag + (size_t)r2 * N_ + u0 + 64 + sg2 * 32);
            #pragma unroll
            for (int j = 0; j < 4; ++j) av[j] = ap[j];
            const int4* bp = reinterpret_cast<const int4*>(Bg + (size_t)(u0 + 64 + r4) * S_ + sg4 * 48);
            #pragma unroll
            for (int j = 0; j < 6; ++j) bv[j] = bp[j];
        }

        #pragma unroll
        for (int ki = 0; ki < 4; ++ki) {
            int k0 = ki * 16;
            uint32_t af[4][4];
            #pragma unroll
            for (int mi = 0; mi < 4; ++mi) {
                int row = wv * 64 + mi * 16 + (lane & 15);
                int col = k0 + ((lane >> 4) << 3);
                uint32_t addr = smem_u32(a_s + row * LDA + col);
                asm volatile("ldmatrix.sync.aligned.m8n8.x4.shared.b16 {%0,%1,%2,%3}, [%4];"
                             : "=r"(af[mi][0]), "=r"(af[mi][1]), "=r"(af[mi][2]), "=r"(af[mi][3])
                             : "r"(addr));
            }
            #pragma unroll
            for (int nj = 0; nj < 3; ++nj) {
                int krow = k0 + ((lane >> 3) & 1) * 8 + (lane & 7);
                int ncol = wf * 48 + nj * 16 + (lane >> 4) * 8;
                uint32_t addr = smem_u32(b_s + krow * LDB + ncol);
                uint32_t q0, q1, q2, q3;
                asm volatile("ldmatrix.sync.aligned.m8n8.x4.trans.shared.b16 {%0,%1,%2,%3}, [%4];"
                             : "=r"(q0), "=r"(q1), "=r"(q2), "=r"(q3) : "r"(addr));
                #pragma unroll
                for (int mi = 0; mi < 4; ++mi) {
                    asm volatile(
                        "mma.sync.aligned.m16n8k16.row.col.f32.f16.f16.f32 "
                        "{%0,%1,%2,%3},{%4,%5,%6,%7},{%8,%9},{%0,%1,%2,%3};"
                        : "+f"(acc[mi][2*nj][0]), "+f"(acc[mi][2*nj][1]),
                          "+f"(acc[mi][2*nj][2]), "+f"(acc[mi][2*nj][3])
                        : "r"(af[mi][0]), "r"(af[mi][1]), "r"(af[mi][2]), "r"(af[mi][3]),
                          "r"(q0), "r"(q1));
                    asm volatile(
                        "mma.sync.aligned.m16n8k16.row.col.f32.f16.f16.f32 "
                        "{%0,%1,%2,%3},{%4,%5,%6,%7},{%8,%9},{%0,%1,%2,%3};"
                        : "+f"(acc[mi][2*nj+1][0]), "+f"(acc[mi][2*nj+1][1]),
                          "+f"(acc[mi][2*nj+1][2]), "+f"(acc[mi][2*nj+1][3])
                        : "r"(af[mi][0]), "r"(af[mi][1]), "r"(af[mi][2]), "r"(af[mi][3]),
                          "r"(q2), "r"(q3));
                }
            }
        }
        __syncthreads();
    }

    #pragma unroll
    for (int mi = 0; mi < 4; ++mi) {
        #pragma unroll
        for (int ni = 0; ni < 6; ++ni) {
            int v = v0 + wv * 64 + mi * 16 + g;
            int f = wf * 48 + ni * 8 + t2;
            float* o0 = outs + (size_t)(c * N_ + v) * S_ + f;
            atomicAdd(o0,     fmaxf(acc[mi][ni][0], 0.f));
            atomicAdd(o0 + 1, fmaxf(acc[mi][ni][1], 0.f));
            float* o1 = outs + (size_t)(c * N_ + v + 8) * S_ + f;
            atomicAdd(o1,     fmaxf(acc[mi][ni][2], 0.f));
            atomicAdd(o1 + 1, fmaxf(acc[mi][ni][3], 0.f));
        }
    }
}

// ---------------- launch ----------------
extern "C" void kernel_launch(void* const* d_in, const int* in_sizes, int n_in,
                              void* d_out, int out_size) {
    const int*   edge = (const int*)d_in[0];
    const float* nf   = (const float*)d_in[1];
    const float* fc   = (const float*)d_in[2];
    const float* asv  = (const float*)d_in[3];
    const float* adv  = (const float*)d_in[4];

    float* outs  = (float*)d_out;                          // (8,1024,3,64)
    float* a_out = outs + (size_t)C_ * N_ * T_ * F_;       // (8,1024,1024,4)

    k_prep<<<1577, 256>>>(outs, fc, asv, adv);
    k_scatter<<<E_ / 256, 256>>>(edge);
    k_av<<<1024, 256>>>(nf);
    k_feat<<<dim3(32, 3, 8), 128>>>(nf, fc);
    k_attn_a<<<dim3(4, N_), 256>>>(a_out);
    k_m<<<dim3(8, 32), 256>>>(outs);
}